// round 15
// baseline (speedup 1.0000x reference)
#include <cuda_runtime.h>
#include <math.h>
#include <stdint.h>

// ---------------- problem constants ----------------
#define B_   2
#define S_   2048
#define DIM_ 1024
#define H_   16
#define KVH_ 4
#define HD_  64
#define I_   2048
#define N_   16
#define DTR_ 64
#define K_   4
#define MTOT (B_*S_)          // 4096
#define EPSF 1.1920929e-07f

// ---------------- scratch (static device, no allocs) ----------------
__device__ float g_mp[MTOT*(size_t)(2*I_)];      // x @ W_mamba.T  (4096 x 4096)
__device__ float g_qh[MTOT*(size_t)DIM_];        // x @ W_q.T
__device__ float g_kv[MTOT*(size_t)(2*KVH_*HD_)];// x @ W_kv.T (k|v)
__device__ float g_qn[MTOT*(size_t)DIM_];        // normed+roped q
__device__ float g_kn[MTOT*(size_t)(KVH_*HD_)];  // normed+roped k
__device__ float g_attn[MTOT*(size_t)DIM_];      // attention out
__device__ float g_u[MTOT*(size_t)I_];           // conv+silu
__device__ float g_params[MTOT*(size_t)96];      // xproj out
__device__ float g_delta[MTOT*(size_t)I_];       // softplus(dt)
__device__ float g_y[MTOT*(size_t)I_];           // scan out (gated)
__device__ float g_merged[MTOT*(size_t)DIM_];    // mamba_out, then alpha-merged
__device__ float g_rcos[S_*32];
__device__ float g_rsin[S_*32];

// ---------------- helpers ----------------
__device__ __forceinline__ float fsig_(float x){ return 1.f/(1.f+__expf(-x)); }
__device__ __forceinline__ float fsoftplus_(float x){
    return fmaxf(x,0.f) + __logf(1.f + __expf(-fabsf(x)));
}
__device__ __forceinline__ float tf32r_(float x){
    uint32_t u; asm("cvt.rna.tf32.f32 %0, %1;" : "=r"(u) : "f"(x));
    return __uint_as_float(u);
}
__device__ __forceinline__ uint32_t tf32u_(float x){
    uint32_t u; asm("cvt.rna.tf32.f32 %0, %1;" : "=r"(u) : "f"(x));
    return u;
}
__device__ __forceinline__ void mma_tf32_(float4& d,
    uint32_t a0, uint32_t a1, uint32_t a2, uint32_t a3,
    uint32_t b0, uint32_t b1)
{
    asm volatile("mma.sync.aligned.m16n8k8.row.col.f32.tf32.tf32.f32 "
        "{%0,%1,%2,%3}, {%4,%5,%6,%7}, {%8,%9}, {%0,%1,%2,%3};\n"
        : "+f"(d.x), "+f"(d.y), "+f"(d.z), "+f"(d.w)
        : "r"(a0), "r"(a1), "r"(a2), "r"(a3), "r"(b0), "r"(b1));
}
__device__ __forceinline__ uint32_t sptr_(const void* p){
    return (uint32_t)__cvta_generic_to_shared(p);
}
#define CP_A16(dst, src, nbytes) \
    asm volatile("cp.async.ca.shared.global [%0], [%1], 16, %2;" \
                 :: "r"(dst), "l"(src), "r"(nbytes))
#define CP_COMMIT() asm volatile("cp.async.commit_group;")
#define CP_WAIT1()  asm volatile("cp.async.wait_group 1;")
#define CP_WAIT2()  asm volatile("cp.async.wait_group 2;")

// ---------------- TF32 TC GEMM, cp.async 3-stage pipeline ----------------
#define TG_LD 36
#define TG_STG (128*TG_LD)
#define TG_SMEM (6*TG_STG*4)   // 3 stages x (A,W) tiles = 110592 bytes

__global__ __launch_bounds__(256, 2)
void tgemm(const float* __restrict__ A, int lda,
           const float* __restrict__ W,
           float* __restrict__ C, int ldc,
           int M, int Nn, int K, int ep,
           const float* __restrict__ bias)
{
    extern __shared__ float smg[];
    float* Asm[3] = { smg,            smg + TG_STG,   smg + 2*TG_STG };
    float* Wsm[3] = { smg + 3*TG_STG, smg + 4*TG_STG, smg + 5*TG_STG };

    const int tid = threadIdx.x;
    const int bm = blockIdx.y * 128;
    const int bn = blockIdx.x * 128;
    const int warp = tid >> 5, lane = tid & 31;
    const int g = lane >> 2, tig = lane & 3;
    const int wm = (warp >> 2) * 64;
    const int wn = (warp & 3) * 32;

    const int lrow = tid >> 1;
    const int lsb  = (tid & 1) * 16;
    const float* Ag = A + (size_t)(bm + lrow) * lda + lsb;
    const int wrow_ld = ((bn + lrow) < Nn) ? (bn + lrow) : (Nn - 1);
    const float* Wg = W + (size_t)wrow_ld * K + lsb;
    const int wbytes = ((bn + lrow) < Nn) ? 16 : 0;
    uint32_t dA[3], dW[3];
    #pragma unroll
    for (int st = 0; st < 3; st++) {
        dA[st] = sptr_(&Asm[st][lrow*TG_LD + lsb]);
        dW[st] = sptr_(&Wsm[st][lrow*TG_LD + lsb]);
    }

    const int NC = K >> 5;

    // prologue: prefetch chunks 0 and 1
    {
        #pragma unroll
        for (int j = 0; j < 4; j++) {
            CP_A16(dA[0] + j*16, Ag + j*4, 16);
            CP_A16(dW[0] + j*16, Wg + j*4, wbytes);
        }
        CP_COMMIT();
        if (NC > 1) {
            #pragma unroll
            for (int j = 0; j < 4; j++) {
                CP_A16(dA[1] + j*16, Ag + 32 + j*4, 16);
                CP_A16(dW[1] + j*16, Wg + 32 + j*4, wbytes);
            }
        }
        CP_COMMIT();
    }

    float4 acc[4][4];
    #pragma unroll
    for (int i = 0; i < 4; i++)
        #pragma unroll
        for (int j = 0; j < 4; j++) acc[i][j] = make_float4(0.f,0.f,0.f,0.f);

    int st_c = 0;      // stage of chunk c
    int st_p = 2;      // stage of chunk c+2
    for (int c = 0; c < NC; c++) {
        if (c + 2 < NC) {
            const float* Ap = Ag + (c+2)*32;
            const float* Wp = Wg + (c+2)*32;
            #pragma unroll
            for (int j = 0; j < 4; j++) {
                CP_A16(dA[st_p] + j*16, Ap + j*4, 16);
                CP_A16(dW[st_p] + j*16, Wp + j*4, wbytes);
            }
        }
        CP_COMMIT();
        CP_WAIT2();
        __syncthreads();

        const float* As = Asm[st_c];
        const float* Ws = Wsm[st_c];

        #pragma unroll
        for (int k0 = 0; k0 < 32; k0 += 8) {
            uint32_t af[4][4], bf[4][2];
            #pragma unroll
            for (int mt = 0; mt < 4; mt++) {
                const float* ar = &As[(wm + mt*16 + g)*TG_LD + k0 + tig];
                af[mt][0] = tf32u_(ar[0]);
                af[mt][1] = tf32u_(ar[8*TG_LD]);
                af[mt][2] = tf32u_(ar[4]);
                af[mt][3] = tf32u_(ar[8*TG_LD + 4]);
            }
            #pragma unroll
            for (int nt = 0; nt < 4; nt++) {
                const float* br = &Ws[(wn + nt*8 + g)*TG_LD + k0 + tig];
                bf[nt][0] = tf32u_(br[0]);
                bf[nt][1] = tf32u_(br[4]);
            }
            #pragma unroll
            for (int mt = 0; mt < 4; mt++)
                #pragma unroll
                for (int nt = 0; nt < 4; nt++)
                    mma_tf32_(acc[mt][nt], af[mt][0], af[mt][1], af[mt][2], af[mt][3],
                              bf[nt][0], bf[nt][1]);
        }
        __syncthreads();

        st_c = (st_c == 2) ? 0 : st_c + 1;
        st_p = (st_p == 2) ? 0 : st_p + 1;
    }

    #pragma unroll
    for (int mt = 0; mt < 4; mt++) {
        int r0 = bm + wm + mt*16 + g;
        #pragma unroll
        for (int nt = 0; nt < 4; nt++) {
            int c0 = bn + wn + nt*8 + 2*tig;
            if (c0 < Nn) {
                float v0 = acc[mt][nt].x, v1 = acc[mt][nt].y;
                float v2 = acc[mt][nt].z, v3 = acc[mt][nt].w;
                if (ep == 1) {
                    float b0v = bias[c0], b1v = bias[c0+1];
                    v0 = fsoftplus_(v0 + b0v); v1 = fsoftplus_(v1 + b1v);
                    v2 = fsoftplus_(v2 + b0v); v3 = fsoftplus_(v3 + b1v);
                }
                *(float2*)(C + (size_t)r0*ldc + c0)     = make_float2(v0, v1);
                *(float2*)(C + (size_t)(r0+8)*ldc + c0) = make_float2(v2, v3);
            }
        }
    }
}

// ---------------- RoPE tables (fp64 for accuracy) ----------------
__global__ void rope_init_k()
{
    int idx = blockIdx.x*256 + threadIdx.x;
    if (idx >= S_*32) return;
    int s = idx >> 5, d = idx & 31;
    double inv = exp(-((double)(2*d)/64.0) * log(10000.0));
    double a = (double)s * inv;
    g_rcos[idx] = (float)cos(a);
    g_rsin[idx] = (float)sin(a);
}

// ---------------- RMSNorm + RoPE (+q_gain) ----------------
__global__ __launch_bounds__(256)
void qk_norm_rope_k(const float* __restrict__ q_gain)
{
    int task = blockIdx.x*8 + (threadIdx.x >> 5);
    int lane = threadIdx.x & 31;
    int m = task / 20, hh = task % 20;
    int s = m & (S_-1);

    const float* src; float* dst;
    if (hh < 16) { src = g_qh + (size_t)m*DIM_ + hh*64; dst = g_qn + (size_t)m*DIM_ + hh*64; }
    else         { src = g_kv + (size_t)m*512 + (hh-16)*64; dst = g_kn + (size_t)m*256 + (hh-16)*64; }

    float v0 = src[lane], v1 = src[lane+32];
    float ss = v0*v0 + v1*v1;
    #pragma unroll
    for (int off = 16; off >= 1; off >>= 1) ss += __shfl_xor_sync(0xffffffffu, ss, off);
    float r = rsqrtf(ss/64.f + EPSF);
    v0 *= r; v1 *= r;
    float c  = g_rcos[s*32 + lane];
    float sn = g_rsin[s*32 + lane];
    float o0 =  v0*c + v1*sn;
    float o1 = -v0*sn + v1*c;
    if (hh < 16) { float g = q_gain[hh]; o0 *= g; o1 *= g; }
    dst[lane] = o0; dst[lane+32] = o1;
}

// ---------------- TF32 TC causal flash attention (round-12 version) ----------------
#define FA_KS0 0
#define FA_KS1 (64*68)
#define FA_VS0 (2*64*68)
#define FA_VS1 (3*64*68)
#define FA_PS  (4*64*68)
#define FA_SMEM ((4*64*68 + 128*68)*4)

__global__ __launch_bounds__(256)
void flash_attn_tc()
{
    extern __shared__ float sm[];
    float* Kbuf[2] = { sm + FA_KS0, sm + FA_KS1 };
    float* Vbuf[2] = { sm + FA_VS0, sm + FA_VS1 };
    float* Ps = sm + FA_PS;

    const int tid = threadIdx.x;
    const int warp = tid >> 5, lane = tid & 31;
    const int g = lane >> 2, tig = lane & 3;
    const int qx = (gridDim.x - 1) - blockIdx.x;
    const int h = blockIdx.y, b = blockIdx.z;
    const int kh = h >> 2;
    const int q0 = qx * 128;
    const int wrow = warp * 16;
    const int r0g = q0 + wrow + g, r1g = r0g + 8;

    uint32_t qf[8][4];
    {
        const float* Qb = g_qn + ((size_t)(b*S_ + q0 + wrow))*DIM_ + h*64;
        #pragma unroll
        for (int ch = 0; ch < 8; ch++) {
            qf[ch][0] = tf32u_(0.125f * Qb[(size_t)(g  )*DIM_ + ch*8 + tig    ]);
            qf[ch][1] = tf32u_(0.125f * Qb[(size_t)(g+8)*DIM_ + ch*8 + tig    ]);
            qf[ch][2] = tf32u_(0.125f * Qb[(size_t)(g  )*DIM_ + ch*8 + tig + 4]);
            qf[ch][3] = tf32u_(0.125f * Qb[(size_t)(g+8)*DIM_ + ch*8 + tig + 4]);
        }
    }

    float4 of[8];
    #pragma unroll
    for (int nb = 0; nb < 8; nb++) of[nb] = make_float4(0.f,0.f,0.f,0.f);
    float m0 = -1e30f, m1 = -1e30f, l0 = 0.f, l1 = 0.f;

    const int KT = 2*qx + 2;
    const int lrow = tid >> 2;
    const int lsb  = (tid & 3) * 16;
    uint32_t dK[2], dV[2];
    #pragma unroll
    for (int st = 0; st < 2; st++) {
        dK[st] = sptr_(&Kbuf[st][lrow*68 + lsb]);
        dV[st] = sptr_(&Vbuf[st][lrow*68 + lsb]);
    }

    {
        size_t krow = (size_t)(b*S_ + lrow);
        const float* kp = g_kn + krow*256 + kh*64 + lsb;
        const float* vp = g_kv + krow*512 + 256 + kh*64 + lsb;
        #pragma unroll
        for (int j = 0; j < 4; j++) {
            CP_A16(dK[0] + j*16, kp + j*4, 16);
            CP_A16(dV[0] + j*16, vp + j*4, 16);
        }
        CP_COMMIT();
    }

    for (int kt = 0; kt < KT; kt++) {
        if (kt + 1 < KT) {
            int st = (kt+1) & 1;
            size_t krow = (size_t)(b*S_ + (kt+1)*64 + lrow);
            const float* kp = g_kn + krow*256 + kh*64 + lsb;
            const float* vp = g_kv + krow*512 + 256 + kh*64 + lsb;
            #pragma unroll
            for (int j = 0; j < 4; j++) {
                CP_A16(dK[st] + j*16, kp + j*4, 16);
                CP_A16(dV[st] + j*16, vp + j*4, 16);
            }
        }
        CP_COMMIT();
        CP_WAIT1();
        __syncthreads();

        const float* Ks = Kbuf[kt & 1];
        const float* Vs = Vbuf[kt & 1];
        const int ktb = kt*64;

        if (ktb <= q0 + wrow + 15) {
            float4 sc[8];
            #pragma unroll
            for (int nb = 0; nb < 8; nb++) sc[nb] = make_float4(0.f,0.f,0.f,0.f);
            #pragma unroll
            for (int ch = 0; ch < 8; ch++) {
                const int k0 = ch*8;
                #pragma unroll
                for (int nb = 0; nb < 8; nb++) {
                    uint32_t b0 = tf32u_(Ks[(nb*8+g)*68 + k0 + tig    ]);
                    uint32_t b1 = tf32u_(Ks[(nb*8+g)*68 + k0 + tig + 4]);
                    mma_tf32_(sc[nb], qf[ch][0], qf[ch][1], qf[ch][2], qf[ch][3], b0, b1);
                }
            }
            if ((ktb + 63) > r0g) {
                #pragma unroll
                for (int nb = 0; nb < 8; nb++) {
                    int c0 = ktb + nb*8 + 2*tig, c1 = c0 + 1;
                    if (c0 > r0g) sc[nb].x = -1e30f;
                    if (c1 > r0g) sc[nb].y = -1e30f;
                    if (c0 > r1g) sc[nb].z = -1e30f;
                    if (c1 > r1g) sc[nb].w = -1e30f;
                }
            }
            float rm0 = -1e30f, rm1 = -1e30f;
            #pragma unroll
            for (int nb = 0; nb < 8; nb++) {
                rm0 = fmaxf(rm0, fmaxf(sc[nb].x, sc[nb].y));
                rm1 = fmaxf(rm1, fmaxf(sc[nb].z, sc[nb].w));
            }
            rm0 = fmaxf(rm0, __shfl_xor_sync(0xffffffffu, rm0, 1));
            rm0 = fmaxf(rm0, __shfl_xor_sync(0xffffffffu, rm0, 2));
            rm1 = fmaxf(rm1, __shfl_xor_sync(0xffffffffu, rm1, 1));
            rm1 = fmaxf(rm1, __shfl_xor_sync(0xffffffffu, rm1, 2));
            float nm0 = fmaxf(m0, rm0), nm1 = fmaxf(m1, rm1);
            float corr0 = __expf(m0 - nm0), corr1 = __expf(m1 - nm1);
            float rs0 = 0.f, rs1 = 0.f;
            #pragma unroll
            for (int nb = 0; nb < 8; nb++) {
                sc[nb].x = __expf(sc[nb].x - nm0);
                sc[nb].y = __expf(sc[nb].y - nm0);
                sc[nb].z = __expf(sc[nb].z - nm1);
                sc[nb].w = __expf(sc[nb].w - nm1);
                rs0 += sc[nb].x + sc[nb].y;
                rs1 += sc[nb].z + sc[nb].w;
            }
            rs0 += __shfl_xor_sync(0xffffffffu, rs0, 1);
            rs0 += __shfl_xor_sync(0xffffffffu, rs0, 2);
            rs1 += __shfl_xor_sync(0xffffffffu, rs1, 1);
            rs1 += __shfl_xor_sync(0xffffffffu, rs1, 2);
            l0 = l0*corr0 + rs0; l1 = l1*corr1 + rs1;
            m0 = nm0; m1 = nm1;
            #pragma unroll
            for (int nb = 0; nb < 8; nb++) {
                of[nb].x *= corr0; of[nb].y *= corr0;
                of[nb].z *= corr1; of[nb].w *= corr1;
            }
            #pragma unroll
            for (int nb = 0; nb < 8; nb++) {
                *(float2*)&Ps[(wrow+g  )*68 + nb*8 + 2*tig] =
                    make_float2(tf32r_(sc[nb].x), tf32r_(sc[nb].y));
                *(float2*)&Ps[(wrow+g+8)*68 + nb*8 + 2*tig] =
                    make_float2(tf32r_(sc[nb].z), tf32r_(sc[nb].w));
            }
            __syncwarp();
            #pragma unroll
            for (int ch = 0; ch < 8; ch++) {
                const int kc = ch*8;
                uint32_t a0 = __float_as_uint(Ps[(wrow+g  )*68 + kc + tig    ]);
                uint32_t a1 = __float_as_uint(Ps[(wrow+g+8)*68 + kc + tig    ]);
                uint32_t a2 = __float_as_uint(Ps[(wrow+g  )*68 + kc + tig + 4]);
                uint32_t a3 = __float_as_uint(Ps[(wrow+g+8)*68 + kc + tig + 4]);
                #pragma unroll
                for (int nb = 0; nb < 8; nb++) {
                    uint32_t b0 = tf32u_(Vs[(kc+tig  )*68 + nb*8 + g]);
                    uint32_t b1 = tf32u_(Vs[(kc+tig+4)*68 + nb*8 + g]);
                    mma_tf32_(of[nb], a0, a1, a2, a3, b0, b1);
                }
            }
        }
        __syncthreads();
    }

    float inv0 = 1.f / l0, inv1 = 1.f / l1;
    float* O0 = g_attn + (size_t)(b*S_ + r0g)*DIM_ + h*64;
    float* O1 = g_attn + (size_t)(b*S_ + r1g)*DIM_ + h*64;
    #pragma unroll
    for (int nb = 0; nb < 8; nb++) {
        *(float2*)(O0 + nb*8 + 2*tig) = make_float2(of[nb].x*inv0, of[nb].y*inv0);
        *(float2*)(O1 + nb*8 + 2*tig) = make_float2(of[nb].z*inv1, of[nb].w*inv1);
    }
}

// ---------------- depthwise causal conv (K=4) + SiLU, float4 vectorized ----------------
#define CONV_STEP(kk, c0, c1, c2, c3)                                        \
    { int sp = s - 3 + (kk);                                                 \
      if (sp >= 0) {                                                         \
          float4 xv = *(const float4*)(g_mp + ((size_t)(b*S_ + sp))*(2*I_) + i); \
          acc.x += xv.x*(c0); acc.y += xv.y*(c1);                            \
          acc.z += xv.z*(c2); acc.w += xv.w*(c3);                            \
      } }

__global__ __launch_bounds__(256)
void conv_silu_k(const float* __restrict__ conv_w, const float* __restrict__ conv_b)
{
    int idx = blockIdx.x*256 + threadIdx.x;      // [0, MTOT*512)
    int m = idx >> 9;
    int i = (idx & 511) << 2;
    int b = m >> 11, s = m & (S_-1);

    float4 acc = *(const float4*)(conv_b + i);
    float4 w0 = *(const float4*)(conv_w + (i+0)*4);
    float4 w1 = *(const float4*)(conv_w + (i+1)*4);
    float4 w2 = *(const float4*)(conv_w + (i+2)*4);
    float4 w3 = *(const float4*)(conv_w + (i+3)*4);

    CONV_STEP(0, w0.x, w1.x, w2.x, w3.x)
    CONV_STEP(1, w0.y, w1.y, w2.y, w3.y)
    CONV_STEP(2, w0.z, w1.z, w2.z, w3.z)
    CONV_STEP(3, w0.w, w1.w, w2.w, w3.w)

    acc.x *= fsig_(acc.x); acc.y *= fsig_(acc.y);
    acc.z *= fsig_(acc.z); acc.w *= fsig_(acc.w);
    *(float4*)(g_u + (size_t)m*I_ + i) = acc;
}

// ---------------- SSM sequential scan: unroll-8 batch-prefetch FIFO ----------------
__global__ __launch_bounds__(256)
void ssm_scan_k(const float* __restrict__ A_log, const float* __restrict__ Dvec)
{
    int gtid = blockIdx.x*256 + threadIdx.x;
    int grp = gtid >> 4, n = gtid & 15;
    int b = grp >> 11, i = grp & (I_-1);

    float A  = -__expf(A_log[i*N_ + n]);
    float Dv = Dvec[i];
    float state = 0.f;
    const bool w0 = (n == 0);

    const float* pd = g_delta  + (size_t)b*S_*I_ + i;
    const float* pu = g_u      + (size_t)b*S_*I_ + i;
    const float* pb = g_params + (size_t)b*S_*96 + 64 + n;
    const float* pg = g_mp     + (size_t)b*S_*(2*I_) + I_ + i;
    float*       py = g_y      + (size_t)b*S_*I_ + i;

    float dq[8], uq[8], Bq[8], Cq[8], gq[8];
    #pragma unroll
    for (int j = 0; j < 8; j++) {
        dq[j] = pd[j*I_];
        uq[j] = pu[j*I_];
        Bq[j] = pb[j*96];
        Cq[j] = pb[j*96 + 16];
        gq[j] = w0 ? pg[j*2*I_] : 0.f;
    }

    for (int t0 = 0; t0 < S_; t0 += 8) {
        float dn[8], un[8], Bn[8], Cn[8], gn[8];
        const bool more = (t0 + 16 <= S_);
        if (more) {
            #pragma unroll
            for (int j = 0; j < 8; j++) {
                dn[j] = pd[(8+j)*I_];
                un[j] = pu[(8+j)*I_];
                Bn[j] = pb[(8+j)*96];
                Cn[j] = pb[(8+j)*96 + 16];
                gn[j] = w0 ? pg[(8+j)*2*I_] : 0.f;
            }
        }

        #pragma unroll
        for (int j = 0; j < 8; j++) {
            state = state*__expf(dq[j]*A) + dq[j]*Bq[j]*uq[j];
            float yv = state*Cq[j];
            yv += __shfl_xor_sync(0xffffffffu, yv, 1);
            yv += __shfl_xor_sync(0xffffffffu, yv, 2);
            yv += __shfl_xor_sync(0xffffffffu, yv, 4);
            yv += __shfl_xor_sync(0xffffffffu, yv, 8);
            if (w0) py[j*I_] = (yv + uq[j]*Dv) * gq[j] * fsig_(gq[j]);
        }

        if (more) {
            #pragma unroll
            for (int j = 0; j < 8; j++) {
                dq[j] = dn[j]; uq[j] = un[j]; Bq[j] = Bn[j]; Cq[j] = Cn[j]; gq[j] = gn[j];
            }
        }
        pd += 8*I_; pu += 8*I_; pb += 8*96; pg += 16*I_; py += 8*I_;
    }
}

// ---------------- alpha-blend: merged = alpha*attn + (1-alpha)*merged ----------------
__global__ __launch_bounds__(256)
void blend_k(const float* __restrict__ alpha_p)
{
    float alpha = fsig_(alpha_p[0]);
    size_t idx = ((size_t)blockIdx.x*256 + threadIdx.x) * 4;
    float4 a = *(const float4*)(g_attn + idx);
    float4 m = *(const float4*)(g_merged + idx);
    m.x = alpha*a.x + (1.f-alpha)*m.x;
    m.y = alpha*a.y + (1.f-alpha)*m.y;
    m.z = alpha*a.z + (1.f-alpha)*m.z;
    m.w = alpha*a.w + (1.f-alpha)*m.w;
    *(float4*)(g_merged + idx) = m;
}

// ---------------- launcher (stream fork/join for branch concurrency) ----------------
extern "C" void kernel_launch(void* const* d_in, const int* in_sizes, int n_in,
                              void* d_out, int out_size)
{
    const float* x        = (const float*)d_in[0];
    const float* W_mamba  = (const float*)d_in[1];
    const float* W_q      = (const float*)d_in[2];
    const float* W_kv     = (const float*)d_in[3];
    const float* q_gain   = (const float*)d_in[4];
    const float* conv_w   = (const float*)d_in[5];
    const float* conv_b   = (const float*)d_in[6];
    const float* W_xproj  = (const float*)d_in[7];
    const float* W_dt     = (const float*)d_in[8];
    const float* b_dt     = (const float*)d_in[9];
    const float* A_log    = (const float*)d_in[10];
    const float* Dvec     = (const float*)d_in[11];
    const float* W_mout   = (const float*)d_in[12];
    const float* W_proj   = (const float*)d_in[13];
    const float* m_alpha  = (const float*)d_in[14];
    float* out = (float*)d_out;

    float *p_mp, *p_qh, *p_kv, *p_u, *p_params, *p_delta, *p_y, *p_merged;
    cudaGetSymbolAddress((void**)&p_mp, g_mp);
    cudaGetSymbolAddress((void**)&p_qh, g_qh);
    cudaGetSymbolAddress((void**)&p_kv, g_kv);
    cudaGetSymbolAddress((void**)&p_u, g_u);
    cudaGetSymbolAddress((void**)&p_params, g_params);
    cudaGetSymbolAddress((void**)&p_delta, g_delta);
    cudaGetSymbolAddress((void**)&p_y, g_y);
    cudaGetSymbolAddress((void**)&p_merged, g_merged);

    cudaFuncSetAttribute(flash_attn_tc, cudaFuncAttributeMaxDynamicSharedMemorySize, FA_SMEM);
    cudaFuncSetAttribute(tgemm, cudaFuncAttributeMaxDynamicSharedMemorySize, TG_SMEM);

    cudaStream_t s1;
    cudaStreamCreate(&s1);
    cudaEvent_t e_fork, e_join;
    cudaEventCreateWithFlags(&e_fork, cudaEventDisableTiming);
    cudaEventCreateWithFlags(&e_join, cudaEventDisableTiming);

    cudaEventRecord(e_fork, 0);
    cudaStreamWaitEvent(s1, e_fork, 0);

    // ---- side branch (attention path) on s1 ----
    rope_init_k<<<(S_*32 + 255)/256, 256, 0, s1>>>();
    tgemm<<<dim3(8,32), 256, TG_SMEM, s1>>>(x, DIM_, W_q, p_qh, DIM_, MTOT, DIM_, DIM_, 0, nullptr);
    tgemm<<<dim3(4,32), 256, TG_SMEM, s1>>>(x, DIM_, W_kv, p_kv, 512, MTOT, 512, DIM_, 0, nullptr);
    qk_norm_rope_k<<<(MTOT*20)/8, 256, 0, s1>>>(q_gain);
    flash_attn_tc<<<dim3(S_/128, H_, B_), 256, FA_SMEM, s1>>>();
    cudaEventRecord(e_join, s1);

    // ---- main branch (mamba path) on default stream ----
    tgemm<<<dim3(32,32), 256, TG_SMEM>>>(x, DIM_, W_mamba, p_mp, 2*I_, MTOT, 2*I_, DIM_, 0, nullptr);
    conv_silu_k<<<(MTOT*(I_/4))/256, 256>>>(conv_w, conv_b);
    tgemm<<<dim3(1,32), 256, TG_SMEM>>>(p_u, I_, W_xproj, p_params, 96, MTOT, 96, I_, 0, nullptr);
    tgemm<<<dim3(16,32), 256, TG_SMEM>>>(p_params, 96, W_dt, p_delta, I_, MTOT, I_, DTR_, 1, b_dt);
    ssm_scan_k<<<(B_*I_*N_)/256, 256>>>(A_log, Dvec);
    tgemm<<<dim3(8,32), 256, TG_SMEM>>>(p_y, I_, W_mout, p_merged, DIM_, MTOT, DIM_, I_, 0, nullptr);

    // join: blend needs attention
    cudaStreamWaitEvent(0, e_join, 0);

    blend_k<<<(MTOT*DIM_/4)/256, 256>>>(m_alpha);
    tgemm<<<dim3(8,32), 256, TG_SMEM>>>(p_merged, DIM_, W_proj, out, DIM_, MTOT, DIM_, DIM_, 0, nullptr);
}

// round 16
// speedup vs baseline: 1.3225x; 1.3225x over previous
#include <cuda_runtime.h>
#include <cuda_fp16.h>
#include <math.h>
#include <stdint.h>

// ---------------- problem constants ----------------
#define B_   2
#define S_   2048
#define DIM_ 1024
#define H_   16
#define KVH_ 4
#define HD_  64
#define I_   2048
#define N_   16
#define DTR_ 64
#define K_   4
#define MTOT (B_*S_)          // 4096
#define EPSF 1.1920929e-07f

// ---------------- scratch (static device, no allocs) ----------------
__device__ float g_mp[MTOT*(size_t)(2*I_)];      // x @ W_mamba.T  (4096 x 4096)
__device__ float g_qh[MTOT*(size_t)DIM_];        // x @ W_q.T
__device__ float g_kv[MTOT*(size_t)(2*KVH_*HD_)];// x @ W_kv.T (k|v)
__device__ float g_qn[MTOT*(size_t)DIM_];        // normed+roped q
__device__ float g_kn[MTOT*(size_t)(KVH_*HD_)];  // normed+roped k
__device__ float g_attn[MTOT*(size_t)DIM_];      // attention out
__device__ float g_u[MTOT*(size_t)I_];           // conv+silu
__device__ float g_params[MTOT*(size_t)96];      // xproj out
__device__ float g_delta[MTOT*(size_t)I_];       // softplus(dt)
__device__ float g_y[MTOT*(size_t)I_];           // scan out (gated)
__device__ float g_merged[MTOT*(size_t)DIM_];    // mamba_out, then alpha-merged
__device__ float g_rcos[S_*32];
__device__ float g_rsin[S_*32];
// fp16 staging for the x-projections
__device__ __half g_xh[MTOT*(size_t)DIM_];
__device__ __half g_wmh[(size_t)(2*I_)*DIM_];
__device__ __half g_wqh[(size_t)DIM_*DIM_];
__device__ __half g_wkvh[(size_t)512*DIM_];

// ---------------- helpers ----------------
__device__ __forceinline__ float fsig_(float x){ return 1.f/(1.f+__expf(-x)); }
__device__ __forceinline__ float fsoftplus_(float x){
    return fmaxf(x,0.f) + __logf(1.f + __expf(-fabsf(x)));
}
__device__ __forceinline__ float tf32r_(float x){
    uint32_t u; asm("cvt.rna.tf32.f32 %0, %1;" : "=r"(u) : "f"(x));
    return __uint_as_float(u);
}
__device__ __forceinline__ uint32_t tf32u_(float x){
    uint32_t u; asm("cvt.rna.tf32.f32 %0, %1;" : "=r"(u) : "f"(x));
    return u;
}
__device__ __forceinline__ void mma_tf32_(float4& d,
    uint32_t a0, uint32_t a1, uint32_t a2, uint32_t a3,
    uint32_t b0, uint32_t b1)
{
    asm volatile("mma.sync.aligned.m16n8k8.row.col.f32.tf32.tf32.f32 "
        "{%0,%1,%2,%3}, {%4,%5,%6,%7}, {%8,%9}, {%0,%1,%2,%3};\n"
        : "+f"(d.x), "+f"(d.y), "+f"(d.z), "+f"(d.w)
        : "r"(a0), "r"(a1), "r"(a2), "r"(a3), "r"(b0), "r"(b1));
}
__device__ __forceinline__ void mma_f16_(float4& d,
    uint32_t a0, uint32_t a1, uint32_t a2, uint32_t a3,
    uint32_t b0, uint32_t b1)
{
    asm volatile("mma.sync.aligned.m16n8k16.row.col.f32.f16.f16.f32 "
        "{%0,%1,%2,%3}, {%4,%5,%6,%7}, {%8,%9}, {%0,%1,%2,%3};\n"
        : "+f"(d.x), "+f"(d.y), "+f"(d.z), "+f"(d.w)
        : "r"(a0), "r"(a1), "r"(a2), "r"(a3), "r"(b0), "r"(b1));
}
__device__ __forceinline__ uint32_t sptr_(const void* p){
    return (uint32_t)__cvta_generic_to_shared(p);
}
#define CP_A16(dst, src, nbytes) \
    asm volatile("cp.async.ca.shared.global [%0], [%1], 16, %2;" \
                 :: "r"(dst), "l"(src), "r"(nbytes))
#define CP_COMMIT() asm volatile("cp.async.commit_group;")
#define CP_WAIT1()  asm volatile("cp.async.wait_group 1;")

// ---------------- fp32 -> fp16 conversion ----------------
__global__ __launch_bounds__(256)
void f2h_k(const float* __restrict__ src, __half* __restrict__ dst)
{
    size_t i = ((size_t)blockIdx.x*256 + threadIdx.x) * 4;
    float4 v = *(const float4*)(src + i);
    __half2 h0 = __floats2half2_rn(v.x, v.y);
    __half2 h1 = __floats2half2_rn(v.z, v.w);
    *(uint2*)(dst + i) = make_uint2(*(uint32_t*)&h0, *(uint32_t*)&h1);
}

// ---------------- FP16 TC GEMM (N multiple of 128), cp.async double-buffered ----------------
// Block 128x128, K-chunk 32 halves, 2-stage. smem half tiles stride 40 halves (conflict-free).
#define HG_LDH 40
#define HG_STG (128*HG_LDH)
#define HG_SMEM (4*HG_STG*2)   // 2 stages x (A,W), halves*2 bytes = 40960

__global__ __launch_bounds__(256, 2)
void hgemm(const __half* __restrict__ A, const __half* __restrict__ W,
           float* __restrict__ C, int ldc, int Nn, int K)
{
    extern __shared__ __half smh[];
    __half* Ash[2] = { smh,            smh + HG_STG };
    __half* Wsh[2] = { smh + 2*HG_STG, smh + 3*HG_STG };

    const int tid = threadIdx.x;
    const int bm = blockIdx.y * 128;
    const int bn = blockIdx.x * 128;
    const int warp = tid >> 5, lane = tid & 31;
    const int g = lane >> 2, tig = lane & 3;
    const int wm = (warp >> 2) * 64;
    const int wn = (warp & 3) * 32;

    // loader: row = tid>>1, half-offset (tid&1)*16 (=32 bytes, two 16B chunks)
    const int lrow = tid >> 1;
    const int lh   = (tid & 1) * 16;
    const __half* Ag = A + (size_t)(bm + lrow) * K + lh;
    const __half* Wg = W + (size_t)(bn + lrow) * K + lh;
    uint32_t dA[2], dW[2];
    #pragma unroll
    for (int st = 0; st < 2; st++) {
        dA[st] = sptr_(&Ash[st][lrow*HG_LDH + lh]);
        dW[st] = sptr_(&Wsh[st][lrow*HG_LDH + lh]);
    }

    const int NC = K >> 5;

    {
        CP_A16(dA[0],      Ag,     16);
        CP_A16(dA[0] + 16, Ag + 8, 16);
        CP_A16(dW[0],      Wg,     16);
        CP_A16(dW[0] + 16, Wg + 8, 16);
        CP_COMMIT();
    }

    float4 acc[4][4];
    #pragma unroll
    for (int i = 0; i < 4; i++)
        #pragma unroll
        for (int j = 0; j < 4; j++) acc[i][j] = make_float4(0.f,0.f,0.f,0.f);

    for (int c = 0; c < NC; c++) {
        if (c + 1 < NC) {
            int st = (c+1) & 1;
            const __half* Ap = Ag + (c+1)*32;
            const __half* Wp = Wg + (c+1)*32;
            CP_A16(dA[st],      Ap,     16);
            CP_A16(dA[st] + 16, Ap + 8, 16);
            CP_A16(dW[st],      Wp,     16);
            CP_A16(dW[st] + 16, Wp + 8, 16);
        }
        CP_COMMIT();
        CP_WAIT1();
        __syncthreads();

        const __half* As = Ash[c & 1];
        const __half* Ws = Wsh[c & 1];

        #pragma unroll
        for (int k0 = 0; k0 < 32; k0 += 16) {
            uint32_t af[4][4], bf[4][2];
            #pragma unroll
            for (int mt = 0; mt < 4; mt++) {
                const __half* ar = &As[(wm + mt*16 + g)*HG_LDH + k0 + 2*tig];
                af[mt][0] = *(const uint32_t*)(ar);
                af[mt][1] = *(const uint32_t*)(ar + 8*HG_LDH);
                af[mt][2] = *(const uint32_t*)(ar + 8);
                af[mt][3] = *(const uint32_t*)(ar + 8*HG_LDH + 8);
            }
            #pragma unroll
            for (int nt = 0; nt < 4; nt++) {
                const __half* br = &Ws[(wn + nt*8 + g)*HG_LDH + k0 + 2*tig];
                bf[nt][0] = *(const uint32_t*)(br);
                bf[nt][1] = *(const uint32_t*)(br + 8);
            }
            #pragma unroll
            for (int mt = 0; mt < 4; mt++)
                #pragma unroll
                for (int nt = 0; nt < 4; nt++)
                    mma_f16_(acc[mt][nt], af[mt][0], af[mt][1], af[mt][2], af[mt][3],
                             bf[nt][0], bf[nt][1]);
        }
        __syncthreads();
    }

    #pragma unroll
    for (int mt = 0; mt < 4; mt++) {
        int r0 = bm + wm + mt*16 + g;
        #pragma unroll
        for (int nt = 0; nt < 4; nt++) {
            int c0 = bn + wn + nt*8 + 2*tig;
            *(float2*)(C + (size_t)r0*ldc + c0)     = make_float2(acc[mt][nt].x, acc[mt][nt].y);
            *(float2*)(C + (size_t)(r0+8)*ldc + c0) = make_float2(acc[mt][nt].z, acc[mt][nt].w);
        }
    }
}

// ---------------- TF32 TC GEMM, cp.async double-buffered (round-12 version) ----------------
#define TG_LD 36
#define TG_STG (128*TG_LD)
#define TG_SMEM (4*TG_STG*4)   // 73728 bytes

__global__ __launch_bounds__(256, 2)
void tgemm(const float* __restrict__ A, int lda,
           const float* __restrict__ W,
           float* __restrict__ C, int ldc,
           int M, int Nn, int K, int ep,
           const float* __restrict__ bias)
{
    extern __shared__ float smg[];
    float* Asm[2] = { smg,            smg + TG_STG };
    float* Wsm[2] = { smg + 2*TG_STG, smg + 3*TG_STG };

    const int tid = threadIdx.x;
    const int bm = blockIdx.y * 128;
    const int bn = blockIdx.x * 128;
    const int warp = tid >> 5, lane = tid & 31;
    const int g = lane >> 2, tig = lane & 3;
    const int wm = (warp >> 2) * 64;
    const int wn = (warp & 3) * 32;

    const int lrow = tid >> 1;
    const int lsb  = (tid & 1) * 16;
    const float* Ag = A + (size_t)(bm + lrow) * lda + lsb;
    const int wrow_ld = ((bn + lrow) < Nn) ? (bn + lrow) : (Nn - 1);
    const float* Wg = W + (size_t)wrow_ld * K + lsb;
    const int wbytes = ((bn + lrow) < Nn) ? 16 : 0;
    uint32_t dA[2], dW[2];
    #pragma unroll
    for (int st = 0; st < 2; st++) {
        dA[st] = sptr_(&Asm[st][lrow*TG_LD + lsb]);
        dW[st] = sptr_(&Wsm[st][lrow*TG_LD + lsb]);
    }

    const int NC = K >> 5;

    {
        #pragma unroll
        for (int j = 0; j < 4; j++) {
            CP_A16(dA[0] + j*16, Ag + j*4, 16);
            CP_A16(dW[0] + j*16, Wg + j*4, wbytes);
        }
        CP_COMMIT();
    }

    float4 acc[4][4];
    #pragma unroll
    for (int i = 0; i < 4; i++)
        #pragma unroll
        for (int j = 0; j < 4; j++) acc[i][j] = make_float4(0.f,0.f,0.f,0.f);

    for (int c = 0; c < NC; c++) {
        if (c + 1 < NC) {
            int st = (c+1) & 1;
            const float* Ap = Ag + (c+1)*32;
            const float* Wp = Wg + (c+1)*32;
            #pragma unroll
            for (int j = 0; j < 4; j++) {
                CP_A16(dA[st] + j*16, Ap + j*4, 16);
                CP_A16(dW[st] + j*16, Wp + j*4, wbytes);
            }
        }
        CP_COMMIT();
        CP_WAIT1();
        __syncthreads();

        const float* As = Asm[c & 1];
        const float* Ws = Wsm[c & 1];

        #pragma unroll
        for (int k0 = 0; k0 < 32; k0 += 8) {
            uint32_t af[4][4], bf[4][2];
            #pragma unroll
            for (int mt = 0; mt < 4; mt++) {
                const float* ar = &As[(wm + mt*16 + g)*TG_LD + k0 + tig];
                af[mt][0] = tf32u_(ar[0]);
                af[mt][1] = tf32u_(ar[8*TG_LD]);
                af[mt][2] = tf32u_(ar[4]);
                af[mt][3] = tf32u_(ar[8*TG_LD + 4]);
            }
            #pragma unroll
            for (int nt = 0; nt < 4; nt++) {
                const float* br = &Ws[(wn + nt*8 + g)*TG_LD + k0 + tig];
                bf[nt][0] = tf32u_(br[0]);
                bf[nt][1] = tf32u_(br[4]);
            }
            #pragma unroll
            for (int mt = 0; mt < 4; mt++)
                #pragma unroll
                for (int nt = 0; nt < 4; nt++)
                    mma_tf32_(acc[mt][nt], af[mt][0], af[mt][1], af[mt][2], af[mt][3],
                              bf[nt][0], bf[nt][1]);
        }
        __syncthreads();
    }

    #pragma unroll
    for (int mt = 0; mt < 4; mt++) {
        int r0 = bm + wm + mt*16 + g;
        #pragma unroll
        for (int nt = 0; nt < 4; nt++) {
            int c0 = bn + wn + nt*8 + 2*tig;
            if (c0 < Nn) {
                float v0 = acc[mt][nt].x, v1 = acc[mt][nt].y;
                float v2 = acc[mt][nt].z, v3 = acc[mt][nt].w;
                if (ep == 1) {
                    float b0v = bias[c0], b1v = bias[c0+1];
                    v0 = fsoftplus_(v0 + b0v); v1 = fsoftplus_(v1 + b1v);
                    v2 = fsoftplus_(v2 + b0v); v3 = fsoftplus_(v3 + b1v);
                }
                *(float2*)(C + (size_t)r0*ldc + c0)     = make_float2(v0, v1);
                *(float2*)(C + (size_t)(r0+8)*ldc + c0) = make_float2(v2, v3);
            }
        }
    }
}

// ---------------- RoPE tables (fp64 for accuracy) ----------------
__global__ void rope_init_k()
{
    int idx = blockIdx.x*256 + threadIdx.x;
    if (idx >= S_*32) return;
    int s = idx >> 5, d = idx & 31;
    double inv = exp(-((double)(2*d)/64.0) * log(10000.0));
    double a = (double)s * inv;
    g_rcos[idx] = (float)cos(a);
    g_rsin[idx] = (float)sin(a);
}

// ---------------- RMSNorm + RoPE (+q_gain) ----------------
__global__ __launch_bounds__(256)
void qk_norm_rope_k(const float* __restrict__ q_gain)
{
    int task = blockIdx.x*8 + (threadIdx.x >> 5);
    int lane = threadIdx.x & 31;
    int m = task / 20, hh = task % 20;
    int s = m & (S_-1);

    const float* src; float* dst;
    if (hh < 16) { src = g_qh + (size_t)m*DIM_ + hh*64; dst = g_qn + (size_t)m*DIM_ + hh*64; }
    else         { src = g_kv + (size_t)m*512 + (hh-16)*64; dst = g_kn + (size_t)m*256 + (hh-16)*64; }

    float v0 = src[lane], v1 = src[lane+32];
    float ss = v0*v0 + v1*v1;
    #pragma unroll
    for (int off = 16; off >= 1; off >>= 1) ss += __shfl_xor_sync(0xffffffffu, ss, off);
    float r = rsqrtf(ss/64.f + EPSF);
    v0 *= r; v1 *= r;
    float c  = g_rcos[s*32 + lane];
    float sn = g_rsin[s*32 + lane];
    float o0 =  v0*c + v1*sn;
    float o1 = -v0*sn + v1*c;
    if (hh < 16) { float g = q_gain[hh]; o0 *= g; o1 *= g; }
    dst[lane] = o0; dst[lane+32] = o1;
}

// ---------------- TF32 TC causal flash attention (round-12 version) ----------------
#define FA_KS0 0
#define FA_KS1 (64*68)
#define FA_VS0 (2*64*68)
#define FA_VS1 (3*64*68)
#define FA_PS  (4*64*68)
#define FA_SMEM ((4*64*68 + 128*68)*4)

__global__ __launch_bounds__(256)
void flash_attn_tc()
{
    extern __shared__ float sm[];
    float* Kbuf[2] = { sm + FA_KS0, sm + FA_KS1 };
    float* Vbuf[2] = { sm + FA_VS0, sm + FA_VS1 };
    float* Ps = sm + FA_PS;

    const int tid = threadIdx.x;
    const int warp = tid >> 5, lane = tid & 31;
    const int g = lane >> 2, tig = lane & 3;
    const int qx = (gridDim.x - 1) - blockIdx.x;
    const int h = blockIdx.y, b = blockIdx.z;
    const int kh = h >> 2;
    const int q0 = qx * 128;
    const int wrow = warp * 16;
    const int r0g = q0 + wrow + g, r1g = r0g + 8;

    uint32_t qf[8][4];
    {
        const float* Qb = g_qn + ((size_t)(b*S_ + q0 + wrow))*DIM_ + h*64;
        #pragma unroll
        for (int ch = 0; ch < 8; ch++) {
            qf[ch][0] = tf32u_(0.125f * Qb[(size_t)(g  )*DIM_ + ch*8 + tig    ]);
            qf[ch][1] = tf32u_(0.125f * Qb[(size_t)(g+8)*DIM_ + ch*8 + tig    ]);
            qf[ch][2] = tf32u_(0.125f * Qb[(size_t)(g  )*DIM_ + ch*8 + tig + 4]);
            qf[ch][3] = tf32u_(0.125f * Qb[(size_t)(g+8)*DIM_ + ch*8 + tig + 4]);
        }
    }

    float4 of[8];
    #pragma unroll
    for (int nb = 0; nb < 8; nb++) of[nb] = make_float4(0.f,0.f,0.f,0.f);
    float m0 = -1e30f, m1 = -1e30f, l0 = 0.f, l1 = 0.f;

    const int KT = 2*qx + 2;
    const int lrow = tid >> 2;
    const int lsb  = (tid & 3) * 16;
    uint32_t dK[2], dV[2];
    #pragma unroll
    for (int st = 0; st < 2; st++) {
        dK[st] = sptr_(&Kbuf[st][lrow*68 + lsb]);
        dV[st] = sptr_(&Vbuf[st][lrow*68 + lsb]);
    }

    {
        size_t krow = (size_t)(b*S_ + lrow);
        const float* kp = g_kn + krow*256 + kh*64 + lsb;
        const float* vp = g_kv + krow*512 + 256 + kh*64 + lsb;
        #pragma unroll
        for (int j = 0; j < 4; j++) {
            CP_A16(dK[0] + j*16, kp + j*4, 16);
            CP_A16(dV[0] + j*16, vp + j*4, 16);
        }
        CP_COMMIT();
    }

    for (int kt = 0; kt < KT; kt++) {
        if (kt + 1 < KT) {
            int st = (kt+1) & 1;
            size_t krow = (size_t)(b*S_ + (kt+1)*64 + lrow);
            const float* kp = g_kn + krow*256 + kh*64 + lsb;
            const float* vp = g_kv + krow*512 + 256 + kh*64 + lsb;
            #pragma unroll
            for (int j = 0; j < 4; j++) {
                CP_A16(dK[st] + j*16, kp + j*4, 16);
                CP_A16(dV[st] + j*16, vp + j*4, 16);
            }
        }
        CP_COMMIT();
        CP_WAIT1();
        __syncthreads();

        const float* Ks = Kbuf[kt & 1];
        const float* Vs = Vbuf[kt & 1];
        const int ktb = kt*64;

        if (ktb <= q0 + wrow + 15) {
            float4 sc[8];
            #pragma unroll
            for (int nb = 0; nb < 8; nb++) sc[nb] = make_float4(0.f,0.f,0.f,0.f);
            #pragma unroll
            for (int ch = 0; ch < 8; ch++) {
                const int k0 = ch*8;
                #pragma unroll
                for (int nb = 0; nb < 8; nb++) {
                    uint32_t b0 = tf32u_(Ks[(nb*8+g)*68 + k0 + tig    ]);
                    uint32_t b1 = tf32u_(Ks[(nb*8+g)*68 + k0 + tig + 4]);
                    mma_tf32_(sc[nb], qf[ch][0], qf[ch][1], qf[ch][2], qf[ch][3], b0, b1);
                }
            }
            if ((ktb + 63) > r0g) {
                #pragma unroll
                for (int nb = 0; nb < 8; nb++) {
                    int c0 = ktb + nb*8 + 2*tig, c1 = c0 + 1;
                    if (c0 > r0g) sc[nb].x = -1e30f;
                    if (c1 > r0g) sc[nb].y = -1e30f;
                    if (c0 > r1g) sc[nb].z = -1e30f;
                    if (c1 > r1g) sc[nb].w = -1e30f;
                }
            }
            float rm0 = -1e30f, rm1 = -1e30f;
            #pragma unroll
            for (int nb = 0; nb < 8; nb++) {
                rm0 = fmaxf(rm0, fmaxf(sc[nb].x, sc[nb].y));
                rm1 = fmaxf(rm1, fmaxf(sc[nb].z, sc[nb].w));
            }
            rm0 = fmaxf(rm0, __shfl_xor_sync(0xffffffffu, rm0, 1));
            rm0 = fmaxf(rm0, __shfl_xor_sync(0xffffffffu, rm0, 2));
            rm1 = fmaxf(rm1, __shfl_xor_sync(0xffffffffu, rm1, 1));
            rm1 = fmaxf(rm1, __shfl_xor_sync(0xffffffffu, rm1, 2));
            float nm0 = fmaxf(m0, rm0), nm1 = fmaxf(m1, rm1);
            float corr0 = __expf(m0 - nm0), corr1 = __expf(m1 - nm1);
            float rs0 = 0.f, rs1 = 0.f;
            #pragma unroll
            for (int nb = 0; nb < 8; nb++) {
                sc[nb].x = __expf(sc[nb].x - nm0);
                sc[nb].y = __expf(sc[nb].y - nm0);
                sc[nb].z = __expf(sc[nb].z - nm1);
                sc[nb].w = __expf(sc[nb].w - nm1);
                rs0 += sc[nb].x + sc[nb].y;
                rs1 += sc[nb].z + sc[nb].w;
            }
            rs0 += __shfl_xor_sync(0xffffffffu, rs0, 1);
            rs0 += __shfl_xor_sync(0xffffffffu, rs0, 2);
            rs1 += __shfl_xor_sync(0xffffffffu, rs1, 1);
            rs1 += __shfl_xor_sync(0xffffffffu, rs1, 2);
            l0 = l0*corr0 + rs0; l1 = l1*corr1 + rs1;
            m0 = nm0; m1 = nm1;
            #pragma unroll
            for (int nb = 0; nb < 8; nb++) {
                of[nb].x *= corr0; of[nb].y *= corr0;
                of[nb].z *= corr1; of[nb].w *= corr1;
            }
            #pragma unroll
            for (int nb = 0; nb < 8; nb++) {
                *(float2*)&Ps[(wrow+g  )*68 + nb*8 + 2*tig] =
                    make_float2(tf32r_(sc[nb].x), tf32r_(sc[nb].y));
                *(float2*)&Ps[(wrow+g+8)*68 + nb*8 + 2*tig] =
                    make_float2(tf32r_(sc[nb].z), tf32r_(sc[nb].w));
            }
            __syncwarp();
            #pragma unroll
            for (int ch = 0; ch < 8; ch++) {
                const int kc = ch*8;
                uint32_t a0 = __float_as_uint(Ps[(wrow+g  )*68 + kc + tig    ]);
                uint32_t a1 = __float_as_uint(Ps[(wrow+g+8)*68 + kc + tig    ]);
                uint32_t a2 = __float_as_uint(Ps[(wrow+g  )*68 + kc + tig + 4]);
                uint32_t a3 = __float_as_uint(Ps[(wrow+g+8)*68 + kc + tig + 4]);
                #pragma unroll
                for (int nb = 0; nb < 8; nb++) {
                    uint32_t b0 = tf32u_(Vs[(kc+tig  )*68 + nb*8 + g]);
                    uint32_t b1 = tf32u_(Vs[(kc+tig+4)*68 + nb*8 + g]);
                    mma_tf32_(of[nb], a0, a1, a2, a3, b0, b1);
                }
            }
        }
        __syncthreads();
    }

    float inv0 = 1.f / l0, inv1 = 1.f / l1;
    float* O0 = g_attn + (size_t)(b*S_ + r0g)*DIM_ + h*64;
    float* O1 = g_attn + (size_t)(b*S_ + r1g)*DIM_ + h*64;
    #pragma unroll
    for (int nb = 0; nb < 8; nb++) {
        *(float2*)(O0 + nb*8 + 2*tig) = make_float2(of[nb].x*inv0, of[nb].y*inv0);
        *(float2*)(O1 + nb*8 + 2*tig) = make_float2(of[nb].z*inv1, of[nb].w*inv1);
    }
}

// ---------------- depthwise causal conv (K=4) + SiLU, float4 vectorized ----------------
#define CONV_STEP(kk, c0, c1, c2, c3)                                        \
    { int sp = s - 3 + (kk);                                                 \
      if (sp >= 0) {                                                         \
          float4 xv = *(const float4*)(g_mp + ((size_t)(b*S_ + sp))*(2*I_) + i); \
          acc.x += xv.x*(c0); acc.y += xv.y*(c1);                            \
          acc.z += xv.z*(c2); acc.w += xv.w*(c3);                            \
      } }

__global__ __launch_bounds__(256)
void conv_silu_k(const float* __restrict__ conv_w, const float* __restrict__ conv_b)
{
    int idx = blockIdx.x*256 + threadIdx.x;
    int m = idx >> 9;
    int i = (idx & 511) << 2;
    int b = m >> 11, s = m & (S_-1);

    float4 acc = *(const float4*)(conv_b + i);
    float4 w0 = *(const float4*)(conv_w + (i+0)*4);
    float4 w1 = *(const float4*)(conv_w + (i+1)*4);
    float4 w2 = *(const float4*)(conv_w + (i+2)*4);
    float4 w3 = *(const float4*)(conv_w + (i+3)*4);

    CONV_STEP(0, w0.x, w1.x, w2.x, w3.x)
    CONV_STEP(1, w0.y, w1.y, w2.y, w3.y)
    CONV_STEP(2, w0.z, w1.z, w2.z, w3.z)
    CONV_STEP(3, w0.w, w1.w, w2.w, w3.w)

    acc.x *= fsig_(acc.x); acc.y *= fsig_(acc.y);
    acc.z *= fsig_(acc.z); acc.w *= fsig_(acc.w);
    *(float4*)(g_u + (size_t)m*I_ + i) = acc;
}

// ---------------- SSM sequential scan: unroll-8 batch-prefetch FIFO ----------------
__global__ __launch_bounds__(256)
void ssm_scan_k(const float* __restrict__ A_log, const float* __restrict__ Dvec)
{
    int gtid = blockIdx.x*256 + threadIdx.x;
    int grp = gtid >> 4, n = gtid & 15;
    int b = grp >> 11, i = grp & (I_-1);

    float A  = -__expf(A_log[i*N_ + n]);
    float Dv = Dvec[i];
    float state = 0.f;
    const bool w0 = (n == 0);

    const float* pd = g_delta  + (size_t)b*S_*I_ + i;
    const float* pu = g_u      + (size_t)b*S_*I_ + i;
    const float* pb = g_params + (size_t)b*S_*96 + 64 + n;
    const float* pg = g_mp     + (size_t)b*S_*(2*I_) + I_ + i;
    float*       py = g_y      + (size_t)b*S_*I_ + i;

    float dq[8], uq[8], Bq[8], Cq[8], gq[8];
    #pragma unroll
    for (int j = 0; j < 8; j++) {
        dq[j] = pd[j*I_];
        uq[j] = pu[j*I_];
        Bq[j] = pb[j*96];
        Cq[j] = pb[j*96 + 16];
        gq[j] = w0 ? pg[j*2*I_] : 0.f;
    }

    for (int t0 = 0; t0 < S_; t0 += 8) {
        float dn[8], un[8], Bn[8], Cn[8], gn[8];
        const bool more = (t0 + 16 <= S_);
        if (more) {
            #pragma unroll
            for (int j = 0; j < 8; j++) {
                dn[j] = pd[(8+j)*I_];
                un[j] = pu[(8+j)*I_];
                Bn[j] = pb[(8+j)*96];
                Cn[j] = pb[(8+j)*96 + 16];
                gn[j] = w0 ? pg[(8+j)*2*I_] : 0.f;
            }
        }

        #pragma unroll
        for (int j = 0; j < 8; j++) {
            state = state*__expf(dq[j]*A) + dq[j]*Bq[j]*uq[j];
            float yv = state*Cq[j];
            yv += __shfl_xor_sync(0xffffffffu, yv, 1);
            yv += __shfl_xor_sync(0xffffffffu, yv, 2);
            yv += __shfl_xor_sync(0xffffffffu, yv, 4);
            yv += __shfl_xor_sync(0xffffffffu, yv, 8);
            if (w0) py[j*I_] = (yv + uq[j]*Dv) * gq[j] * fsig_(gq[j]);
        }

        if (more) {
            #pragma unroll
            for (int j = 0; j < 8; j++) {
                dq[j] = dn[j]; uq[j] = un[j]; Bq[j] = Bn[j]; Cq[j] = Cn[j]; gq[j] = gn[j];
            }
        }
        pd += 8*I_; pu += 8*I_; pb += 8*96; pg += 16*I_; py += 8*I_;
    }
}

// ---------------- alpha-blend: merged = alpha*attn + (1-alpha)*merged ----------------
__global__ __launch_bounds__(256)
void blend_k(const float* __restrict__ alpha_p)
{
    float alpha = fsig_(alpha_p[0]);
    size_t idx = ((size_t)blockIdx.x*256 + threadIdx.x) * 4;
    float4 a = *(const float4*)(g_attn + idx);
    float4 m = *(const float4*)(g_merged + idx);
    m.x = alpha*a.x + (1.f-alpha)*m.x;
    m.y = alpha*a.y + (1.f-alpha)*m.y;
    m.z = alpha*a.z + (1.f-alpha)*m.z;
    m.w = alpha*a.w + (1.f-alpha)*m.w;
    *(float4*)(g_merged + idx) = m;
}

// ---------------- launcher (stream fork/join for branch concurrency) ----------------
extern "C" void kernel_launch(void* const* d_in, const int* in_sizes, int n_in,
                              void* d_out, int out_size)
{
    const float* x        = (const float*)d_in[0];
    const float* W_mamba  = (const float*)d_in[1];
    const float* W_q      = (const float*)d_in[2];
    const float* W_kv     = (const float*)d_in[3];
    const float* q_gain   = (const float*)d_in[4];
    const float* conv_w   = (const float*)d_in[5];
    const float* conv_b   = (const float*)d_in[6];
    const float* W_xproj  = (const float*)d_in[7];
    const float* W_dt     = (const float*)d_in[8];
    const float* b_dt     = (const float*)d_in[9];
    const float* A_log    = (const float*)d_in[10];
    const float* Dvec     = (const float*)d_in[11];
    const float* W_mout   = (const float*)d_in[12];
    const float* W_proj   = (const float*)d_in[13];
    const float* m_alpha  = (const float*)d_in[14];
    float* out = (float*)d_out;

    float *p_mp, *p_qh, *p_kv, *p_u, *p_params, *p_delta, *p_y, *p_merged;
    __half *p_xh, *p_wmh, *p_wqh, *p_wkvh;
    cudaGetSymbolAddress((void**)&p_mp, g_mp);
    cudaGetSymbolAddress((void**)&p_qh, g_qh);
    cudaGetSymbolAddress((void**)&p_kv, g_kv);
    cudaGetSymbolAddress((void**)&p_u, g_u);
    cudaGetSymbolAddress((void**)&p_params, g_params);
    cudaGetSymbolAddress((void**)&p_delta, g_delta);
    cudaGetSymbolAddress((void**)&p_y, g_y);
    cudaGetSymbolAddress((void**)&p_merged, g_merged);
    cudaGetSymbolAddress((void**)&p_xh, g_xh);
    cudaGetSymbolAddress((void**)&p_wmh, g_wmh);
    cudaGetSymbolAddress((void**)&p_wqh, g_wqh);
    cudaGetSymbolAddress((void**)&p_wkvh, g_wkvh);

    cudaFuncSetAttribute(flash_attn_tc, cudaFuncAttributeMaxDynamicSharedMemorySize, FA_SMEM);
    cudaFuncSetAttribute(tgemm, cudaFuncAttributeMaxDynamicSharedMemorySize, TG_SMEM);
    cudaFuncSetAttribute(hgemm, cudaFuncAttributeMaxDynamicSharedMemorySize, HG_SMEM);

    cudaStream_t s1;
    cudaStreamCreate(&s1);
    cudaEvent_t e_fork, e_join;
    cudaEventCreateWithFlags(&e_fork, cudaEventDisableTiming);
    cudaEventCreateWithFlags(&e_join, cudaEventDisableTiming);

    // ---- fp16 conversion pre-pass (before fork: both branches consume) ----
    f2h_k<<<(MTOT*DIM_/4)/256, 256>>>(x, p_xh);
    f2h_k<<<(2*I_*DIM_/4)/256, 256>>>(W_mamba, p_wmh);
    f2h_k<<<(DIM_*DIM_/4)/256, 256>>>(W_q, p_wqh);
    f2h_k<<<(512*DIM_/4)/256, 256>>>(W_kv, p_wkvh);

    cudaEventRecord(e_fork, 0);
    cudaStreamWaitEvent(s1, e_fork, 0);

    // ---- side branch (attention path) on s1 ----
    rope_init_k<<<(S_*32 + 255)/256, 256, 0, s1>>>();
    hgemm<<<dim3(8,32), 256, HG_SMEM, s1>>>(p_xh, p_wqh, p_qh, DIM_, DIM_, DIM_);
    hgemm<<<dim3(4,32), 256, HG_SMEM, s1>>>(p_xh, p_wkvh, p_kv, 512, 512, DIM_);
    qk_norm_rope_k<<<(MTOT*20)/8, 256, 0, s1>>>(q_gain);
    flash_attn_tc<<<dim3(S_/128, H_, B_), 256, FA_SMEM, s1>>>();
    cudaEventRecord(e_join, s1);

    // ---- main branch (mamba path) on default stream ----
    hgemm<<<dim3(32,32), 256, HG_SMEM>>>(p_xh, p_wmh, p_mp, 2*I_, 2*I_, DIM_);
    conv_silu_k<<<(MTOT*(I_/4))/256, 256>>>(conv_w, conv_b);
    tgemm<<<dim3(1,32), 256, TG_SMEM>>>(p_u, I_, W_xproj, p_params, 96, MTOT, 96, I_, 0, nullptr);
    tgemm<<<dim3(16,32), 256, TG_SMEM>>>(p_params, 96, W_dt, p_delta, I_, MTOT, I_, DTR_, 1, b_dt);
    ssm_scan_k<<<(B_*I_*N_)/256, 256>>>(A_log, Dvec);
    tgemm<<<dim3(8,32), 256, TG_SMEM>>>(p_y, I_, W_mout, p_merged, DIM_, MTOT, DIM_, I_, 0, nullptr);

    // join: blend needs attention
    cudaStreamWaitEvent(0, e_join, 0);

    blend_k<<<(MTOT*DIM_/4)/256, 256>>>(m_alpha);
    tgemm<<<dim3(8,32), 256, TG_SMEM>>>(p_merged, DIM_, W_proj, out, DIM_, MTOT, DIM_, DIM_, 0, nullptr);
}